// round 1
// baseline (speedup 1.0000x reference)
#include <cuda_runtime.h>
#include <cstddef>

// Problem constants (fixed by the reference).
#define BB 4
#define CC 512
#define NN_ 4096
#define C8 64

// Scratch (allocation-free rule: __device__ globals).
__device__ float g_q[(size_t)BB * C8 * NN_];          // qT: [B, 64, N]
__device__ float g_k[(size_t)BB * C8 * NN_];          // k : [B, 64, N]
__device__ float g_v[(size_t)BB * CC * NN_];          // v : [B, 512, N]
__device__ float g_att[(size_t)BB * NN_ * NN_];       // att/score: [B, N, N]

// ---------------------------------------------------------------------------
// Generic tiled SGEMM:
//   C[b, m, n] = alpha * sum_k A(m,k) * B(k,n)  (+ bias[m]) (+ resid[b,m,n])
// A_KM: A stored k-major, element A[k*lda + m]; else A[m*lda + k].
// B_KM: B stored k-major, element B[k*ldb + n]; else B[n*ldb + k].
// All dims assumed multiples of the tile sizes (true for this problem).
// ---------------------------------------------------------------------------
template <int BM, int BN, int BK, int TM, int TN, bool A_KM, bool B_KM>
__global__ void __launch_bounds__((BM / TM) * (BN / TN))
gemm_kernel(const float* __restrict__ A, const float* __restrict__ B,
            float* __restrict__ C, int K, int lda, int ldb, int ldc,
            size_t sA, size_t sB, size_t sC,
            const float* __restrict__ bias,
            const float* __restrict__ resid, size_t sR,
            const float* __restrict__ gamma) {
    constexpr int NT = (BM / TM) * (BN / TN);
    __shared__ float As[BK][BM + 4];
    __shared__ float Bs[BK][BN + 4];

    const int tid = threadIdx.x;
    const int tx = tid % (BN / TN);
    const int ty = tid / (BN / TN);
    const int bm = blockIdx.y * BM;
    const int bn = blockIdx.x * BN;
    const int b = blockIdx.z;

    A += (size_t)b * sA;
    B += (size_t)b * sB;

    float acc[TM][TN];
#pragma unroll
    for (int i = 0; i < TM; i++)
#pragma unroll
        for (int j = 0; j < TN; j++) acc[i][j] = 0.f;

    for (int k0 = 0; k0 < K; k0 += BK) {
        // Stage A tile -> As[k][m]
#pragma unroll
        for (int t = 0; t < BM * BK / NT; t++) {
            int idx = tid + t * NT;
            if constexpr (A_KM) {
                int m = idx % BM, k = idx / BM;
                As[k][m] = A[(size_t)(k0 + k) * lda + (bm + m)];
            } else {
                int k = idx % BK, m = idx / BK;
                As[k][m] = A[(size_t)(bm + m) * lda + (k0 + k)];
            }
        }
        // Stage B tile -> Bs[k][n]
#pragma unroll
        for (int t = 0; t < BN * BK / NT; t++) {
            int idx = tid + t * NT;
            if constexpr (B_KM) {
                int n = idx % BN, k = idx / BN;
                Bs[k][n] = B[(size_t)(k0 + k) * ldb + (bn + n)];
            } else {
                int k = idx % BK, n = idx / BK;
                Bs[k][n] = B[(size_t)(bn + n) * ldb + (k0 + k)];
            }
        }
        __syncthreads();

#pragma unroll
        for (int kk = 0; kk < BK; kk++) {
            float a[TM], bv[TN];
#pragma unroll
            for (int i = 0; i < TM / 4; i++)
                *reinterpret_cast<float4*>(&a[i * 4]) =
                    *reinterpret_cast<const float4*>(&As[kk][ty * TM + i * 4]);
#pragma unroll
            for (int j = 0; j < TN / 4; j++)
                *reinterpret_cast<float4*>(&bv[j * 4]) =
                    *reinterpret_cast<const float4*>(&Bs[kk][tx * TN + j * 4]);
#pragma unroll
            for (int i = 0; i < TM; i++)
#pragma unroll
                for (int j = 0; j < TN; j++) acc[i][j] += a[i] * bv[j];
        }
        __syncthreads();
    }

    const float alpha = gamma ? *gamma : 1.0f;
#pragma unroll
    for (int i = 0; i < TM; i++) {
        const int m = bm + ty * TM + i;
        const float bia = bias ? bias[m] : 0.f;
#pragma unroll
        for (int j = 0; j < TN; j++) {
            const int n = bn + tx * TN + j;
            float val = alpha * acc[i][j] + bia;
            if (resid) val += resid[(size_t)b * sR + (size_t)m * ldc + n];
            C[(size_t)b * sC + (size_t)m * ldc + n] = val;
        }
    }
}

// ---------------------------------------------------------------------------
// Row softmax over last dim (in place). One block per row of length NN_.
// ---------------------------------------------------------------------------
__global__ void __launch_bounds__(256) softmax_kernel(float* __restrict__ att) {
    __shared__ float red[8];
    float* p = att + (size_t)blockIdx.x * NN_;
    const int tid = threadIdx.x;
    const int lane = tid & 31, warp = tid >> 5;

    float m = -1e30f;
    for (int j = tid; j < NN_; j += 256) m = fmaxf(m, p[j]);
#pragma unroll
    for (int o = 16; o > 0; o >>= 1) m = fmaxf(m, __shfl_xor_sync(0xffffffffu, m, o));
    if (lane == 0) red[warp] = m;
    __syncthreads();
    m = red[0];
#pragma unroll
    for (int w = 1; w < 8; w++) m = fmaxf(m, red[w]);

    float s = 0.f;
    for (int j = tid; j < NN_; j += 256) {
        float e = __expf(p[j] - m);
        p[j] = e;
        s += e;
    }
#pragma unroll
    for (int o = 16; o > 0; o >>= 1) s += __shfl_xor_sync(0xffffffffu, s, o);
    __syncthreads();
    if (lane == 0) red[warp] = s;
    __syncthreads();
    s = red[0];
#pragma unroll
    for (int w = 1; w < 8; w++) s += red[w];
    const float inv = 1.0f / s;

    for (int j = tid; j < NN_; j += 256) p[j] *= inv;
}

// ---------------------------------------------------------------------------
extern "C" void kernel_launch(void* const* d_in, const int* in_sizes, int n_in,
                              void* d_out, int out_size) {
    const float* x = (const float*)d_in[0];
    const float* Wq = (const float*)d_in[1];
    const float* bq = (const float*)d_in[2];
    const float* Wk = (const float*)d_in[3];
    const float* bk = (const float*)d_in[4];
    const float* Wv = (const float*)d_in[5];
    const float* bv = (const float*)d_in[6];
    const float* gamma = (const float*)d_in[7];
    float* out = (float*)d_out;

    float *q, *k, *v, *att;
    cudaGetSymbolAddress((void**)&q, g_q);
    cudaGetSymbolAddress((void**)&k, g_k);
    cudaGetSymbolAddress((void**)&v, g_v);
    cudaGetSymbolAddress((void**)&att, g_att);

    const size_t sX = (size_t)CC * NN_;     // per-batch x stride
    const size_t sQK = (size_t)C8 * NN_;    // per-batch q/k stride
    const size_t sAtt = (size_t)NN_ * NN_;  // per-batch att stride

    // qT[b,o,n] = Wq @ x[b] + bq   (M=64, N=4096, K=512) — NN layout
    gemm_kernel<64, 64, 16, 4, 4, false, true>
        <<<dim3(NN_ / 64, C8 / 64, BB), 256>>>(
            Wq, x, q, CC, CC, NN_, NN_, 0, sX, sQK, bq, nullptr, 0, nullptr);

    // k[b,o,n] = Wk @ x[b] + bk
    gemm_kernel<64, 64, 16, 4, 4, false, true>
        <<<dim3(NN_ / 64, C8 / 64, BB), 256>>>(
            Wk, x, k, CC, CC, NN_, NN_, 0, sX, sQK, bk, nullptr, 0, nullptr);

    // v[b,c,n] = Wv @ x[b] + bv   (M=512, N=4096, K=512)
    gemm_kernel<128, 64, 16, 8, 4, false, true>
        <<<dim3(NN_ / 64, CC / 128, BB), 256>>>(
            Wv, x, v, CC, CC, NN_, NN_, 0, sX, sX, bv, nullptr, 0, nullptr);

    // att[b,i,j] = sum_o qT[b,o,i] * k[b,o,j]   (M=N=4096, K=64) — TN layout
    gemm_kernel<64, 64, 16, 4, 4, true, true>
        <<<dim3(NN_ / 64, NN_ / 64, BB), 256>>>(
            q, k, att, C8, NN_, NN_, NN_, sQK, sQK, sAtt,
            nullptr, nullptr, 0, nullptr);

    // softmax over j, in place
    softmax_kernel<<<BB * NN_, 256>>>(att);

    // out[b,c,i] = gamma * sum_j v[b,c,j] * score[b,i,j] + x[b,c,i]
    //   (M=512, N=4096, K=4096) — NT layout (both operands j-major)
    gemm_kernel<128, 64, 16, 8, 4, false, false>
        <<<dim3(NN_ / 64, CC / 128, BB), 256>>>(
            v, att, out, NN_, NN_, NN_, NN_, sX, sAtt, sX,
            nullptr, x, sX, gamma);
}

// round 5
// speedup vs baseline: 2.0792x; 2.0792x over previous
#include <cuda_runtime.h>
#include <cuda_bf16.h>
#include <cstdint>
#include <cstddef>

#define BB 4
#define CC 512
#define NN_ 4096
#define C8 64

// ---------------- scratch (__device__ globals; allocation-free rule) -------
__device__ __align__(128) __nv_bfloat16 g_xth[(size_t)BB * NN_ * CC];  // x^T hi [b,n,c]
__device__ __align__(128) __nv_bfloat16 g_xtl[(size_t)BB * NN_ * CC];  // x^T lo
__device__ __align__(128) __nv_bfloat16 g_wqh[C8 * CC], g_wql[C8 * CC];
__device__ __align__(128) __nv_bfloat16 g_wkh[C8 * CC], g_wkl[C8 * CC];
__device__ __align__(128) __nv_bfloat16 g_wvh[CC * CC], g_wvl[CC * CC];
__device__ __align__(128) __nv_bfloat16 g_qth[(size_t)BB * NN_ * C8]; // q^T [b,n,o]
__device__ __align__(128) __nv_bfloat16 g_qtl[(size_t)BB * NN_ * C8];
__device__ __align__(128) __nv_bfloat16 g_kth[(size_t)BB * NN_ * C8]; // k^T [b,n,o]
__device__ __align__(128) __nv_bfloat16 g_ktl[(size_t)BB * NN_ * C8];
__device__ __align__(128) __nv_bfloat16 g_vh[(size_t)BB * CC * NN_];  // v [b,c,n]
__device__ __align__(128) __nv_bfloat16 g_vl[(size_t)BB * CC * NN_];
__device__ __align__(128) float g_att[(size_t)BB * NN_ * NN_];        // att [b,i,j]
__device__ __align__(128) __nv_bfloat16 g_sh[(size_t)BB * NN_ * NN_]; // score [b,i,j]
__device__ __align__(128) __nv_bfloat16 g_sl[(size_t)BB * NN_ * NN_];

// ---------------- helpers ---------------------------------------------------
__device__ __forceinline__ uint32_t smem_u32(const void* p) {
    uint32_t a;
    asm("{ .reg .u64 t; cvta.to.shared.u64 t, %1; cvt.u32.u64 %0, t; }"
        : "=r"(a) : "l"(p));
    return a;
}
__device__ __forceinline__ void cp16(uint32_t dst, const void* src) {
    asm volatile("cp.async.cg.shared.global [%0], [%1], 16;" :: "r"(dst), "l"(src));
}
__device__ __forceinline__ void mma16816(float* d, const uint32_t* a, const uint32_t* b) {
    asm volatile(
        "mma.sync.aligned.m16n8k16.row.col.f32.bf16.bf16.f32 "
        "{%0,%1,%2,%3}, {%4,%5,%6,%7}, {%8,%9}, {%0,%1,%2,%3};"
        : "+f"(d[0]), "+f"(d[1]), "+f"(d[2]), "+f"(d[3])
        : "r"(a[0]), "r"(a[1]), "r"(a[2]), "r"(a[3]), "r"(b[0]), "r"(b[1]));
}
__device__ __forceinline__ void split_bf16(float v, __nv_bfloat16& h, __nv_bfloat16& l) {
    h = __float2bfloat16(v);
    l = __float2bfloat16(v - __bfloat162float(h));
}

// ---------------------------------------------------------------------------
// Split-bf16 HMMA GEMM.
//   C[b,m,n] = sum_k A(m,k)*B(n,k)   (3-MMA split emulation, fp32 accum)
// A stored [m][k] (lda), B stored [n][k] (ldb), both as hi/lo bf16 pairs.
// Epilogue options: +bias[m]; gamma*acc + resid; split-bf16 output; transposed
// output ([n][m], ldc = m-stride).
// Block: 256 threads = 8 warps (2 x 4). Warp tile (BM/2) x (BN/4). BK = 32.
// ---------------------------------------------------------------------------
template <int BM, int BN, bool TRANS_OUT, bool SPLIT_OUT, bool HAS_BIAS, bool HAS_RESID>
__global__ void __launch_bounds__(256)
mma_gemm(const __nv_bfloat16* __restrict__ Ah, const __nv_bfloat16* __restrict__ Al,
         const __nv_bfloat16* __restrict__ Bh, const __nv_bfloat16* __restrict__ Bl,
         int K, int lda, int ldb, size_t sA, size_t sB,
         const float* __restrict__ bias,
         float* __restrict__ Cf,
         __nv_bfloat16* __restrict__ Oh, __nv_bfloat16* __restrict__ Ol,
         int ldc, size_t sC,
         const float* __restrict__ resid, const float* __restrict__ gamma) {
    constexpr int LDSS = 40;               // padded k-stride (bf16) — conflict-free
    constexpr int A_HALF = BM * LDSS;      // elems per (stage,half)
    constexpr int B_HALF = BN * LDSS;
    extern __shared__ __nv_bfloat16 sm[];
    __nv_bfloat16* sAp = sm;               // [2 stages][2 halves][BM][LDSS]
    __nv_bfloat16* sBp = sm + 4 * A_HALF;  // [2 stages][2 halves][BN][LDSS]

    const int tid = threadIdx.x;
    const int lane = tid & 31, warp = tid >> 5;
    const int wm = warp >> 2, wn = warp & 3;
    constexpr int WTM = BM / 2, WTN = BN / 4;
    constexpr int MT = WTM / 16, NT = WTN / 8;

    const int bm0 = blockIdx.y * BM, bn0 = blockIdx.x * BN, b = blockIdx.z;
    const __nv_bfloat16* aptr[2] = {Ah + (size_t)b * sA, Al + (size_t)b * sA};
    const __nv_bfloat16* bptr[2] = {Bh + (size_t)b * sB, Bl + (size_t)b * sB};
    const uint32_t smb = smem_u32(sm);

    float acc[MT][NT][4];
#pragma unroll
    for (int i = 0; i < MT; i++)
#pragma unroll
        for (int j = 0; j < NT; j++)
#pragma unroll
            for (int e = 0; e < 4; e++) acc[i][j][e] = 0.f;

    auto load_stage = [&](int stage, int kt) {
        constexpr int CA = BM * 8 / 256;   // 16B chunks per thread, A
#pragma unroll
        for (int i = 0; i < CA; i++) {
            int idx = tid + i * 256;
            int half = idx / (BM * 4);
            int rem = idx - half * BM * 4;
            int r = rem >> 2, seg = rem & 3;
            const __nv_bfloat16* src =
                aptr[half] + (size_t)(bm0 + r) * lda + kt * 32 + seg * 8;
            uint32_t dst = smb + ((stage * 2 + half) * A_HALF + r * LDSS + seg * 8) * 2;
            cp16(dst, src);
        }
        constexpr int CB = BN * 8 / 256;
#pragma unroll
        for (int i = 0; i < CB; i++) {
            int idx = tid + i * 256;
            int half = idx / (BN * 4);
            int rem = idx - half * BN * 4;
            int r = rem >> 2, seg = rem & 3;
            const __nv_bfloat16* src =
                bptr[half] + (size_t)(bn0 + r) * ldb + kt * 32 + seg * 8;
            uint32_t dst = smb +
                (4 * A_HALF + (stage * 2 + half) * B_HALF + r * LDSS + seg * 8) * 2;
            cp16(dst, src);
        }
        asm volatile("cp.async.commit_group;" ::: "memory");
    };

    const int KT = K / 32;
    load_stage(0, 0);
    const int rbase = wm * WTM + (lane >> 2);
    const int cbase = wn * WTN + (lane >> 2);
    const int kq = (lane & 3) * 2;

    for (int kt = 0; kt < KT; kt++) {
        const int stage = kt & 1;
        if (kt + 1 < KT) {
            load_stage(stage ^ 1, kt + 1);
            asm volatile("cp.async.wait_group 1;" ::: "memory");
        } else {
            asm volatile("cp.async.wait_group 0;" ::: "memory");
        }
        __syncthreads();

#pragma unroll
        for (int ks = 0; ks < 2; ks++) {
            const int kk = ks * 16 + kq;
            uint32_t bh[NT][2], bl[NT][2];
#pragma unroll
            for (int nt = 0; nt < NT; nt++) {
                const __nv_bfloat16* ph =
                    sBp + (stage * 2) * B_HALF + (cbase + nt * 8) * LDSS + kk;
                bh[nt][0] = *(const uint32_t*)(ph);
                bh[nt][1] = *(const uint32_t*)(ph + 8);
                const __nv_bfloat16* pl = ph + B_HALF;
                bl[nt][0] = *(const uint32_t*)(pl);
                bl[nt][1] = *(const uint32_t*)(pl + 8);
            }
#pragma unroll
            for (int mt = 0; mt < MT; mt++) {
                const __nv_bfloat16* ph =
                    sAp + (stage * 2) * A_HALF + (rbase + mt * 16) * LDSS + kk;
                uint32_t ah[4], al[4];
                ah[0] = *(const uint32_t*)(ph);
                ah[1] = *(const uint32_t*)(ph + 8 * LDSS);
                ah[2] = *(const uint32_t*)(ph + 8);
                ah[3] = *(const uint32_t*)(ph + 8 * LDSS + 8);
                const __nv_bfloat16* pl = ph + A_HALF;
                al[0] = *(const uint32_t*)(pl);
                al[1] = *(const uint32_t*)(pl + 8 * LDSS);
                al[2] = *(const uint32_t*)(pl + 8);
                al[3] = *(const uint32_t*)(pl + 8 * LDSS + 8);
#pragma unroll
                for (int nt = 0; nt < NT; nt++) {
                    mma16816(acc[mt][nt], ah, bh[nt]);
                    mma16816(acc[mt][nt], ah, bl[nt]);
                    mma16816(acc[mt][nt], al, bh[nt]);
                }
            }
        }
        __syncthreads();
    }

    float g = 1.f;
    if constexpr (HAS_RESID) g = __ldg(gamma);

#pragma unroll
    for (int mt = 0; mt < MT; mt++) {
        const int r = bm0 + wm * WTM + mt * 16 + (lane >> 2);
        float bi0 = 0.f, bi1 = 0.f;
        if constexpr (HAS_BIAS) { bi0 = bias[r]; bi1 = bias[r + 8]; }
#pragma unroll
        for (int nt = 0; nt < NT; nt++) {
            const int c = bn0 + wn * WTN + nt * 8 + (lane & 3) * 2;
            float v[4] = {acc[mt][nt][0] + bi0, acc[mt][nt][1] + bi0,
                          acc[mt][nt][2] + bi1, acc[mt][nt][3] + bi1};
            if constexpr (!TRANS_OUT) {
#pragma unroll
                for (int p = 0; p < 2; p++) {   // row pairs: (r), (r+8)
                    const int row = r + p * 8;
                    size_t idx = (size_t)b * sC + (size_t)row * ldc + c;
                    if constexpr (SPLIT_OUT) {
                        __nv_bfloat16 h0, l0, h1, l1;
                        split_bf16(v[p * 2 + 0], h0, l0);
                        split_bf16(v[p * 2 + 1], h1, l1);
                        *reinterpret_cast<__nv_bfloat162*>(&Oh[idx]) =
                            __nv_bfloat162(h0, h1);
                        *reinterpret_cast<__nv_bfloat162*>(&Ol[idx]) =
                            __nv_bfloat162(l0, l1);
                    } else {
                        float2 o;
                        if constexpr (HAS_RESID) {
                            float2 rx = *reinterpret_cast<const float2*>(&resid[idx]);
                            o.x = g * v[p * 2 + 0] + rx.x;
                            o.y = g * v[p * 2 + 1] + rx.y;
                        } else {
                            o.x = v[p * 2 + 0];
                            o.y = v[p * 2 + 1];
                        }
                        *reinterpret_cast<float2*>(&Cf[idx]) = o;
                    }
                }
            } else {
                const int rr[4] = {r, r, r + 8, r + 8};
                const int ccx[4] = {c, c + 1, c, c + 1};
#pragma unroll
                for (int e = 0; e < 4; e++) {
                    size_t idx = (size_t)b * sC + (size_t)ccx[e] * ldc + rr[e];
                    if constexpr (SPLIT_OUT) {
                        __nv_bfloat16 h, l;
                        split_bf16(v[e], h, l);
                        Oh[idx] = h;
                        Ol[idx] = l;
                    } else {
                        Cf[idx] = v[e];
                    }
                }
            }
        }
    }
}

// ---------------------------------------------------------------------------
// x [b,c,n] fp32 -> x^T [b,n,c] split bf16 (tiled transpose).
// ---------------------------------------------------------------------------
__global__ void __launch_bounds__(256)
transpose_split_x(const float* __restrict__ x,
                  __nv_bfloat16* __restrict__ th, __nv_bfloat16* __restrict__ tl) {
    __shared__ float t[32][33];
    const int b = blockIdx.z;
    const int c0 = blockIdx.y * 32, n0 = blockIdx.x * 32;
    const float* xp = x + (size_t)b * CC * NN_;
#pragma unroll
    for (int i = threadIdx.y; i < 32; i += 8)
        t[i][threadIdx.x] = xp[(size_t)(c0 + i) * NN_ + n0 + threadIdx.x];
    __syncthreads();
    __nv_bfloat16* hp = th + (size_t)b * NN_ * CC;
    __nv_bfloat16* lp = tl + (size_t)b * NN_ * CC;
#pragma unroll
    for (int i = threadIdx.y; i < 32; i += 8) {
        float v = t[threadIdx.x][i];
        __nv_bfloat16 h, l;
        split_bf16(v, h, l);
        size_t idx = (size_t)(n0 + i) * CC + c0 + threadIdx.x;
        hp[idx] = h;
        lp[idx] = l;
    }
}

__global__ void __launch_bounds__(256)
split_arr(const float* __restrict__ s, __nv_bfloat16* __restrict__ h,
          __nv_bfloat16* __restrict__ l, int n) {
    int i = blockIdx.x * 256 + threadIdx.x;
    if (i < n) {
        __nv_bfloat16 hh, ll;
        split_bf16(s[i], hh, ll);
        h[i] = hh;
        l[i] = ll;
    }
}

// ---------------------------------------------------------------------------
// Softmax: fp32 att row -> split-bf16 score row (row cached in smem).
// ---------------------------------------------------------------------------
__global__ void __launch_bounds__(256)
softmax_split_kernel(const float* __restrict__ att,
                     __nv_bfloat16* __restrict__ sh, __nv_bfloat16* __restrict__ sl) {
    __shared__ float rowbuf[NN_];
    __shared__ float red[8];
    const size_t row = blockIdx.x;
    const float* p = att + row * NN_;
    const int tid = threadIdx.x, lane = tid & 31, warp = tid >> 5;

    float m = -1e30f;
    for (int j = tid; j < NN_; j += 256) {
        float v = p[j];
        rowbuf[j] = v;
        m = fmaxf(m, v);
    }
#pragma unroll
    for (int o = 16; o > 0; o >>= 1) m = fmaxf(m, __shfl_xor_sync(0xffffffffu, m, o));
    if (lane == 0) red[warp] = m;
    __syncthreads();
    m = red[0];
#pragma unroll
    for (int w = 1; w < 8; w++) m = fmaxf(m, red[w]);

    float s = 0.f;
    for (int j = tid; j < NN_; j += 256) {
        float e = __expf(rowbuf[j] - m);
        rowbuf[j] = e;
        s += e;
    }
#pragma unroll
    for (int o = 16; o > 0; o >>= 1) s += __shfl_xor_sync(0xffffffffu, s, o);
    __syncthreads();
    if (lane == 0) red[warp] = s;
    __syncthreads();
    s = red[0];
#pragma unroll
    for (int w = 1; w < 8; w++) s += red[w];
    const float inv = 1.0f / s;

    for (int j = tid; j < NN_; j += 256) {
        float v = rowbuf[j] * inv;
        __nv_bfloat16 h, l;
        split_bf16(v, h, l);
        sh[row * NN_ + j] = h;
        sl[row * NN_ + j] = l;
    }
}

// ---------------------------------------------------------------------------
extern "C" void kernel_launch(void* const* d_in, const int* in_sizes, int n_in,
                              void* d_out, int out_size) {
    const float* x = (const float*)d_in[0];
    const float* Wq = (const float*)d_in[1];
    const float* bq = (const float*)d_in[2];
    const float* Wk = (const float*)d_in[3];
    const float* bk = (const float*)d_in[4];
    const float* Wv = (const float*)d_in[5];
    const float* bv = (const float*)d_in[6];
    const float* gamma = (const float*)d_in[7];
    float* out = (float*)d_out;

    __nv_bfloat16 *xth, *xtl, *wqh, *wql, *wkh, *wkl, *wvh, *wvl;
    __nv_bfloat16 *qth, *qtl, *kth, *ktl, *vh, *vl, *sh, *sl;
    float* att;
    cudaGetSymbolAddress((void**)&xth, g_xth);
    cudaGetSymbolAddress((void**)&xtl, g_xtl);
    cudaGetSymbolAddress((void**)&wqh, g_wqh);
    cudaGetSymbolAddress((void**)&wql, g_wql);
    cudaGetSymbolAddress((void**)&wkh, g_wkh);
    cudaGetSymbolAddress((void**)&wkl, g_wkl);
    cudaGetSymbolAddress((void**)&wvh, g_wvh);
    cudaGetSymbolAddress((void**)&wvl, g_wvl);
    cudaGetSymbolAddress((void**)&qth, g_qth);
    cudaGetSymbolAddress((void**)&qtl, g_qtl);
    cudaGetSymbolAddress((void**)&kth, g_kth);
    cudaGetSymbolAddress((void**)&ktl, g_ktl);
    cudaGetSymbolAddress((void**)&vh, g_vh);
    cudaGetSymbolAddress((void**)&vl, g_vl);
    cudaGetSymbolAddress((void**)&sh, g_sh);
    cudaGetSymbolAddress((void**)&sl, g_sl);
    cudaGetSymbolAddress((void**)&att, g_att);

    constexpr int SM128 = 320 * (128 + 128);  // 81920 B
    constexpr int SM64 = 320 * (64 + 128);    // 61440 B
    cudaFuncSetAttribute(mma_gemm<64, 128, true, true, true, false>,
                         cudaFuncAttributeMaxDynamicSharedMemorySize, SM64);
    cudaFuncSetAttribute(mma_gemm<128, 128, false, true, true, false>,
                         cudaFuncAttributeMaxDynamicSharedMemorySize, SM128);
    cudaFuncSetAttribute(mma_gemm<128, 128, false, false, false, false>,
                         cudaFuncAttributeMaxDynamicSharedMemorySize, SM128);
    cudaFuncSetAttribute(mma_gemm<128, 128, false, false, false, true>,
                         cudaFuncAttributeMaxDynamicSharedMemorySize, SM128);

    const size_t sX = (size_t)CC * NN_;
    const size_t sXT = (size_t)NN_ * CC;
    const size_t sQT = (size_t)NN_ * C8;
    const size_t sAtt = (size_t)NN_ * NN_;

    // 0. splits
    transpose_split_x<<<dim3(NN_ / 32, CC / 32, BB), dim3(32, 8)>>>(x, xth, xtl);
    split_arr<<<(C8 * CC + 255) / 256, 256>>>(Wq, wqh, wql, C8 * CC);
    split_arr<<<(C8 * CC + 255) / 256, 256>>>(Wk, wkh, wkl, C8 * CC);
    split_arr<<<(CC * CC + 255) / 256, 256>>>(Wv, wvh, wvl, CC * CC);

    // 1. q^T[b,n,o] = (Wq @ x[b])^T + bq   (M=64, N=4096, K=512), split out
    mma_gemm<64, 128, true, true, true, false>
        <<<dim3(NN_ / 128, 1, BB), 256, SM64>>>(
            wqh, wql, xth, xtl, CC, CC, CC, 0, sXT, bq,
            nullptr, qth, qtl, C8, sQT, nullptr, nullptr);

    // 2. k^T[b,n,o]
    mma_gemm<64, 128, true, true, true, false>
        <<<dim3(NN_ / 128, 1, BB), 256, SM64>>>(
            wkh, wkl, xth, xtl, CC, CC, CC, 0, sXT, bk,
            nullptr, kth, ktl, C8, sQT, nullptr, nullptr);

    // 3. v[b,c,n] = Wv @ x[b] + bv  (M=512, N=4096, K=512), split out
    mma_gemm<128, 128, false, true, true, false>
        <<<dim3(NN_ / 128, CC / 128, BB), 256, SM128>>>(
            wvh, wvl, xth, xtl, CC, CC, CC, 0, sXT, bv,
            nullptr, vh, vl, NN_, sX, nullptr, nullptr);

    // 4. att[b,i,j] = q^T[b,i,:] . k^T[b,j,:]  (M=N=4096, K=64), fp32 out
    mma_gemm<128, 128, false, false, false, false>
        <<<dim3(NN_ / 128, NN_ / 128, BB), 256, SM128>>>(
            qth, qtl, kth, ktl, C8, C8, C8, sQT, sQT, nullptr,
            att, nullptr, nullptr, NN_, sAtt, nullptr, nullptr);

    // 5. softmax over j -> split bf16
    softmax_split_kernel<<<BB * NN_, 256>>>(att, sh, sl);

    // 6. out[b,c,i] = gamma * sum_j v[b,c,j]*score[b,i,j] + x[b,c,i]
    //    (M=512, N=4096, K=4096)
    mma_gemm<128, 128, false, false, false, true>
        <<<dim3(NN_ / 128, CC / 128, BB), 256, SM128>>>(
            vh, vl, sh, sl, NN_, NN_, NN_, sX, sAtt, nullptr,
            out, nullptr, nullptr, NN_, sX, x, gamma);
}